// round 2
// baseline (speedup 1.0000x reference)
#include <cuda_runtime.h>

#define NUM_GRAPHS 512
#define D 128
#define H 256
#define ROWS_PER_BLOCK 512
#define SEG_THREADS 256
#define GPB 4   // graphs per block in MLP kernel

// Scratch (allocation-free rule: __device__ globals)
__device__ float g_S[NUM_GRAPHS * D];    // per-graph feature sums
__device__ float g_val[NUM_GRAPHS];      // per-graph final confidence

// ---------------------------------------------------------------------------
__global__ void zero_kernel() {
    int i = blockIdx.x * blockDim.x + threadIdx.x;
    if (i < NUM_GRAPHS * D / 4)
        reinterpret_cast<float4*>(g_S)[i] = make_float4(0.f, 0.f, 0.f, 0.f);
}

// ---------------------------------------------------------------------------
// Segment sum over sorted batch (int32 ids). 8 row-groups of 32 lanes per
// block; each lane owns 4 dims (float4). Register-accumulate runs of equal
// graph id, flush with atomicAdd only at boundaries / loop end.
__global__ void segsum_kernel(const float4* __restrict__ x4,
                              const int* __restrict__ batch, int N) {
    const int lane = threadIdx.x & 31;
    const int grp  = threadIdx.x >> 5;           // 0..7
    const int blockStart = blockIdx.x * ROWS_PER_BLOCK;
    const int blockEnd   = min(N, blockStart + ROWS_PER_BLOCK);

    float4 acc = make_float4(0.f, 0.f, 0.f, 0.f);
    int cur = -1;

    #pragma unroll 4
    for (int n = blockStart + grp; n < blockEnd; n += 8) {
        int g = batch[n];
        float4 v = x4[(size_t)n * (D / 4) + lane];
        if (g != cur) {
            if (cur >= 0) {
                float* p = &g_S[cur * D + lane * 4];
                atomicAdd(p + 0, acc.x); atomicAdd(p + 1, acc.y);
                atomicAdd(p + 2, acc.z); atomicAdd(p + 3, acc.w);
            }
            cur = g;
            acc = v;
        } else {
            acc.x += v.x; acc.y += v.y; acc.z += v.z; acc.w += v.w;
        }
    }
    if (cur >= 0) {
        float* p = &g_S[cur * D + lane * 4];
        atomicAdd(p + 0, acc.x); atomicAdd(p + 1, acc.y);
        atomicAdd(p + 2, acc.z); atomicAdd(p + 3, acc.w);
    }
}

// ---------------------------------------------------------------------------
__device__ __forceinline__ int lower_bound_i(const int* __restrict__ a,
                                             int n, int v) {
    int lo = 0, hi = n;
    while (lo < hi) {
        int mid = (lo + hi) >> 1;
        if (a[mid] < v) lo = mid + 1; else hi = mid;
    }
    return lo;
}

// Per-graph MLP: h1 = relu(S@W1+b1); h2 = relu((cnt*h1)@W2+b2);
// c = h2@Wc + bc; out = sp/(1+sp), sp = softplus(c) (stable form).
// One block handles GPB graphs; thread t owns output column t.
__global__ void mlp_kernel(const int* __restrict__ batch, int N,
                           const float* __restrict__ W1, const float* __restrict__ b1,
                           const float* __restrict__ W2, const float* __restrict__ b2,
                           const float* __restrict__ Wc, const float* __restrict__ bc) {
    __shared__ float sS[GPB][D];
    __shared__ float sH[GPB][H];
    __shared__ float scnt[GPB];

    const int g0 = blockIdx.x * GPB;
    const int t  = threadIdx.x;   // 0..H-1 (256 threads)

    // load per-graph sums into shared
    for (int i = t; i < GPB * D; i += H)
        sS[i / D][i % D] = g_S[(g0 + i / D) * D + (i % D)];

    // node counts via binary search on sorted batch
    if (t < GPB) {
        int g = g0 + t;
        int lo = lower_bound_i(batch, N, g);
        int hi = lower_bound_i(batch, N, g + 1);
        scnt[t] = (float)(hi - lo);
    }
    __syncthreads();

    // Layer 1: column t for all GPB graphs
    float acc1[GPB];
    #pragma unroll
    for (int q = 0; q < GPB; q++) acc1[q] = b1[t];
    #pragma unroll 8
    for (int k = 0; k < D; k++) {
        float w = W1[k * H + t];
        #pragma unroll
        for (int q = 0; q < GPB; q++) acc1[q] = fmaf(sS[q][k], w, acc1[q]);
    }
    #pragma unroll
    for (int q = 0; q < GPB; q++)
        sH[q][t] = fmaxf(acc1[q], 0.f) * scnt[q];   // relu then scale by count (agg2)
    __syncthreads();

    // Layer 2
    float acc2[GPB];
    #pragma unroll
    for (int q = 0; q < GPB; q++) acc2[q] = b2[t];
    #pragma unroll 8
    for (int k = 0; k < H; k++) {
        float w = W2[k * H + t];
        #pragma unroll
        for (int q = 0; q < GPB; q++) acc2[q] = fmaf(sH[q][k], w, acc2[q]);
    }

    // confidence head partial: relu(h2[t]) * Wc[t]
    float wc = Wc[t];
    float part[GPB];
    #pragma unroll
    for (int q = 0; q < GPB; q++) part[q] = fmaxf(acc2[q], 0.f) * wc;

    __syncthreads();   // done reading sH as h1; reuse for reduction
    #pragma unroll
    for (int q = 0; q < GPB; q++) sH[q][t] = part[q];
    __syncthreads();

    #pragma unroll
    for (int s = H / 2; s > 0; s >>= 1) {
        if (t < s) {
            #pragma unroll
            for (int q = 0; q < GPB; q++) sH[q][t] += sH[q][t + s];
        }
        __syncthreads();
    }

    if (t < GPB) {
        float c  = sH[t][0] + bc[0];
        // stable softplus: max(c,0) + log1p(exp(-|c|))
        float sp = fmaxf(c, 0.f) + log1pf(expf(-fabsf(c)));
        g_val[g0 + t] = sp / (1.f + sp);
    }
}

// ---------------------------------------------------------------------------
__global__ void scatter_kernel(const int* __restrict__ batch,
                               float* __restrict__ out, int N) {
    int n = blockIdx.x * blockDim.x + threadIdx.x;
    if (n < N) out[n] = g_val[batch[n]];
}

// ---------------------------------------------------------------------------
extern "C" void kernel_launch(void* const* d_in, const int* in_sizes, int n_in,
                              void* d_out, int out_size) {
    const float* x     = (const float*)d_in[0];
    const int*   batch = (const int*)d_in[1];
    const float* W1    = (const float*)d_in[2];
    const float* b1    = (const float*)d_in[3];
    const float* W2    = (const float*)d_in[4];
    const float* b2    = (const float*)d_in[5];
    const float* Wc    = (const float*)d_in[6];
    const float* bc    = (const float*)d_in[7];
    float*       out   = (float*)d_out;

    const int N = in_sizes[1];   // number of nodes (batch length)

    zero_kernel<<<(NUM_GRAPHS * D / 4 + 255) / 256, 256>>>();

    int segBlocks = (N + ROWS_PER_BLOCK - 1) / ROWS_PER_BLOCK;
    segsum_kernel<<<segBlocks, SEG_THREADS>>>(
        reinterpret_cast<const float4*>(x), batch, N);

    mlp_kernel<<<NUM_GRAPHS / GPB, H>>>(batch, N, W1, b1, W2, b2, Wc, bc);

    scatter_kernel<<<(N + 255) / 256, 256>>>(batch, out, N);
}

// round 3
// speedup vs baseline: 1.2039x; 1.2039x over previous
#include <cuda_runtime.h>

#define NUM_GRAPHS 512
#define D 128
#define H 256
#define RPB 256          // rows per segsum block (8 warps x 32 rows)
#define GPB 4            // graphs per MLP block

// Scratch (allocation-free rule: __device__ globals; zero-initialized at load,
// re-zeroed at the end of every run by scatter_kernel)
__device__ float g_S[NUM_GRAPHS * D];    // per-graph feature sums
__device__ float g_val[NUM_GRAPHS];      // per-graph final confidence

// ---------------------------------------------------------------------------
__device__ __forceinline__ void flush_acc(int g, int lane, float4 a) {
    float* p = &g_S[g * D + lane * 4];
    atomicAdd(p + 0, a.x);
    atomicAdd(p + 1, a.y);
    atomicAdd(p + 2, a.z);
    atomicAdd(p + 3, a.w);
}

// Segment sum over sorted batch (int32 ids).
// Each block covers RPB contiguous rows; batch ids staged in smem.
// Warp w owns 32 contiguous rows; each lane owns one float4 column chunk.
// Fast path (single graph in window): branch-free batched-load loop.
__global__ void segsum_kernel(const float4* __restrict__ x4,
                              const int* __restrict__ batch, int N) {
    __shared__ int sb[RPB];
    const int t = threadIdx.x;
    const int blockStart = blockIdx.x * RPB;
    const int rows = min(N - blockStart, RPB);

    if (t < rows) sb[t] = batch[blockStart + t];
    __syncthreads();

    const int lane = t & 31;
    const int warp = t >> 5;
    const int r0 = warp * 32;
    if (r0 >= rows) return;
    const int r1 = min(r0 + 32, rows);

    const float4* xp = x4 + (size_t)blockStart * (D / 4) + lane;

    const int gF = sb[r0];
    const int gL = sb[r1 - 1];

    if (gF == gL) {
        // Entire window belongs to one graph: no branches, loads batch freely.
        float4 a0 = make_float4(0.f, 0.f, 0.f, 0.f);
        float4 a1 = make_float4(0.f, 0.f, 0.f, 0.f);
        int i = r0;
        #pragma unroll 4
        for (; i + 1 < r1; i += 2) {
            float4 v0 = xp[(size_t)i * (D / 4)];
            float4 v1 = xp[(size_t)(i + 1) * (D / 4)];
            a0.x += v0.x; a0.y += v0.y; a0.z += v0.z; a0.w += v0.w;
            a1.x += v1.x; a1.y += v1.y; a1.z += v1.z; a1.w += v1.w;
        }
        if (i < r1) {
            float4 v = xp[(size_t)i * (D / 4)];
            a0.x += v.x; a0.y += v.y; a0.z += v.z; a0.w += v.w;
        }
        a0.x += a1.x; a0.y += a1.y; a0.z += a1.z; a0.w += a1.w;
        flush_acc(gF, lane, a0);
    } else {
        // Window spans >=2 graphs: generic run-length loop (warp-uniform branch).
        float4 acc = make_float4(0.f, 0.f, 0.f, 0.f);
        int cur = gF;
        for (int i = r0; i < r1; i++) {
            int g = sb[i];
            float4 v = xp[(size_t)i * (D / 4)];
            if (g != cur) {
                flush_acc(cur, lane, acc);
                cur = g;
                acc = v;
            } else {
                acc.x += v.x; acc.y += v.y; acc.z += v.z; acc.w += v.w;
            }
        }
        flush_acc(cur, lane, acc);
    }
}

// ---------------------------------------------------------------------------
__device__ __forceinline__ int lower_bound_i(const int* __restrict__ a,
                                             int n, int v) {
    int lo = 0, hi = n;
    while (lo < hi) {
        int mid = (lo + hi) >> 1;
        if (a[mid] < v) lo = mid + 1; else hi = mid;
    }
    return lo;
}

// Per-graph MLP: h1 = relu(S@W1+b1); h2 = relu((cnt*h1)@W2+b2);
// c = h2@Wc + bc; out = sp/(1+sp), sp = softplus(c) (stable form).
__global__ void mlp_kernel(const int* __restrict__ batch, int N,
                           const float* __restrict__ W1, const float* __restrict__ b1,
                           const float* __restrict__ W2, const float* __restrict__ b2,
                           const float* __restrict__ Wc, const float* __restrict__ bc) {
    __shared__ float sS[GPB][D];
    __shared__ float sH[GPB][H];
    __shared__ float scnt[GPB];

    const int g0 = blockIdx.x * GPB;
    const int t  = threadIdx.x;   // 0..H-1 (256 threads)

    for (int i = t; i < GPB * D; i += H)
        sS[i / D][i % D] = g_S[(g0 + i / D) * D + (i % D)];

    if (t < GPB) {
        int g = g0 + t;
        int lo = lower_bound_i(batch, N, g);
        int hi = lower_bound_i(batch, N, g + 1);
        scnt[t] = (float)(hi - lo);
    }
    __syncthreads();

    // Layer 1
    float acc1[GPB];
    #pragma unroll
    for (int q = 0; q < GPB; q++) acc1[q] = b1[t];
    #pragma unroll 8
    for (int k = 0; k < D; k++) {
        float w = W1[k * H + t];
        #pragma unroll
        for (int q = 0; q < GPB; q++) acc1[q] = fmaf(sS[q][k], w, acc1[q]);
    }
    #pragma unroll
    for (int q = 0; q < GPB; q++)
        sH[q][t] = fmaxf(acc1[q], 0.f) * scnt[q];   // relu, then count-scale = agg2
    __syncthreads();

    // Layer 2
    float acc2[GPB];
    #pragma unroll
    for (int q = 0; q < GPB; q++) acc2[q] = b2[t];
    #pragma unroll 8
    for (int k = 0; k < H; k++) {
        float w = W2[k * H + t];
        #pragma unroll
        for (int q = 0; q < GPB; q++) acc2[q] = fmaf(sH[q][k], w, acc2[q]);
    }

    // Confidence head partials
    float wc = Wc[t];
    float part[GPB];
    #pragma unroll
    for (int q = 0; q < GPB; q++) part[q] = fmaxf(acc2[q], 0.f) * wc;

    __syncthreads();
    #pragma unroll
    for (int q = 0; q < GPB; q++) sH[q][t] = part[q];
    __syncthreads();

    #pragma unroll
    for (int s = H / 2; s > 0; s >>= 1) {
        if (t < s) {
            #pragma unroll
            for (int q = 0; q < GPB; q++) sH[q][t] += sH[q][t + s];
        }
        __syncthreads();
    }

    if (t < GPB) {
        float c  = sH[t][0] + bc[0];
        float sp = fmaxf(c, 0.f) + log1pf(expf(-fabsf(c)));
        g_val[g0 + t] = sp / (1.f + sp);
    }
}

// ---------------------------------------------------------------------------
// Scatter: 4 nodes per thread (int4 batch load, 4 independent gathers,
// float4 store). Also re-zeroes g_S for the next graph replay.
__global__ void scatter_kernel(const int* __restrict__ batch,
                               float* __restrict__ out, int N) {
    const int i = blockIdx.x * blockDim.x + threadIdx.x;

    // zero g_S for next replay (16384 float4s)
    if (i < NUM_GRAPHS * D / 4)
        reinterpret_cast<float4*>(g_S)[i] = make_float4(0.f, 0.f, 0.f, 0.f);

    const int n0 = i * 4;
    if (n0 + 3 < N) {
        int4 b = reinterpret_cast<const int4*>(batch)[i];
        float4 o;
        o.x = g_val[b.x];
        o.y = g_val[b.y];
        o.z = g_val[b.z];
        o.w = g_val[b.w];
        reinterpret_cast<float4*>(out)[i] = o;
    } else {
        for (int n = n0; n < N; n++) out[n] = g_val[batch[n]];
    }
}

// ---------------------------------------------------------------------------
extern "C" void kernel_launch(void* const* d_in, const int* in_sizes, int n_in,
                              void* d_out, int out_size) {
    const float* x     = (const float*)d_in[0];
    const int*   batch = (const int*)d_in[1];
    const float* W1    = (const float*)d_in[2];
    const float* b1    = (const float*)d_in[3];
    const float* W2    = (const float*)d_in[4];
    const float* b2    = (const float*)d_in[5];
    const float* Wc    = (const float*)d_in[6];
    const float* bc    = (const float*)d_in[7];
    float*       out   = (float*)d_out;

    const int N = in_sizes[1];

    int segBlocks = (N + RPB - 1) / RPB;
    segsum_kernel<<<segBlocks, RPB>>>(
        reinterpret_cast<const float4*>(x), batch, N);

    mlp_kernel<<<NUM_GRAPHS / GPB, H>>>(batch, N, W1, b1, W2, b2, Wc, bc);

    // scatter also needs >= 16384 threads to zero g_S
    int scThreads = 128;
    int scBlocks  = (N / 4 + scThreads - 1) / scThreads + 1;  // +1 covers exact tail
    if (scBlocks * scThreads < NUM_GRAPHS * D / 4)
        scBlocks = (NUM_GRAPHS * D / 4 + scThreads - 1) / scThreads;
    scatter_kernel<<<scBlocks, scThreads>>>(batch, out, N);
}

// round 4
// speedup vs baseline: 1.2688x; 1.0539x over previous
#include <cuda_runtime.h>

#define NUM_GRAPHS 512
#define D 128
#define H 256
#define RPB 128          // rows per segsum block (4 warps x 32 rows)
#define GPB 4            // graphs per MLP block

// Scratch (allocation-free rule: __device__ globals; zero-initialized at load,
// re-zeroed by mlp_kernel after consumption so every graph replay starts clean)
__device__ float g_S[NUM_GRAPHS * D];    // per-graph feature sums

// ---------------------------------------------------------------------------
__device__ __forceinline__ void facc(float4& a, float4 v) {
    a.x += v.x; a.y += v.y; a.z += v.z; a.w += v.w;
}
__device__ __forceinline__ void flush_acc(int g, int lane, float4 a) {
    float* p = &g_S[g * D + lane * 4];
    atomicAdd(p + 0, a.x);
    atomicAdd(p + 1, a.y);
    atomicAdd(p + 2, a.z);
    atomicAdd(p + 3, a.w);
}

// Segment sum over sorted batch (int32 ids).
// Each block: RPB contiguous rows, batch ids staged in smem.
// Warp w owns 32 contiguous rows; lane owns one float4 column chunk.
// Fast path (window is one graph): 4 independent accumulators, 4-wide load
// batches, unroll 2 -> 8 independent LDG.128 in flight per warp.
__global__ __launch_bounds__(RPB) void segsum_kernel(
        const float4* __restrict__ x4, const int* __restrict__ batch, int N) {
    __shared__ int sb[RPB];
    const int t = threadIdx.x;
    const int blockStart = blockIdx.x * RPB;
    const int rows = min(N - blockStart, RPB);

    if (t < rows) sb[t] = batch[blockStart + t];
    __syncthreads();

    const int lane = t & 31;
    const int warp = t >> 5;
    const int r0 = warp * 32;
    if (r0 >= rows) return;
    const int r1 = min(r0 + 32, rows);

    const float4* xp = x4 + (size_t)blockStart * (D / 4) + lane;

    const int gF = sb[r0];
    const int gL = sb[r1 - 1];

    if (gF == gL) {
        float4 a0 = make_float4(0.f, 0.f, 0.f, 0.f);
        float4 a1 = a0, a2 = a0, a3 = a0;
        int i = r0;
        #pragma unroll 2
        for (; i + 3 < r1; i += 4) {
            float4 v0 = xp[(size_t)(i + 0) * (D / 4)];
            float4 v1 = xp[(size_t)(i + 1) * (D / 4)];
            float4 v2 = xp[(size_t)(i + 2) * (D / 4)];
            float4 v3 = xp[(size_t)(i + 3) * (D / 4)];
            facc(a0, v0); facc(a1, v1); facc(a2, v2); facc(a3, v3);
        }
        for (; i < r1; i++) facc(a0, xp[(size_t)i * (D / 4)]);
        facc(a0, a1); facc(a2, a3); facc(a0, a2);
        flush_acc(gF, lane, a0);
    } else {
        // Window spans >=2 graphs: run-length loop (warp-uniform branch).
        float4 acc = make_float4(0.f, 0.f, 0.f, 0.f);
        int cur = gF;
        for (int i = r0; i < r1; i++) {
            int g = sb[i];
            float4 v = xp[(size_t)i * (D / 4)];
            if (g != cur) {
                flush_acc(cur, lane, acc);
                cur = g;
                acc = v;
            } else {
                facc(acc, v);
            }
        }
        flush_acc(cur, lane, acc);
    }
}

// ---------------------------------------------------------------------------
__device__ __forceinline__ int lower_bound_i(const int* __restrict__ a,
                                             int n, int v) {
    int lo = 0, hi = n;
    while (lo < hi) {
        int mid = (lo + hi) >> 1;
        if (a[mid] < v) lo = mid + 1; else hi = mid;
    }
    return lo;
}

// Per-graph MLP + fused scatter + g_S re-zero.
// h1 = relu(S@W1+b1); h2 = relu((cnt*h1)@W2+b2); c = h2@Wc+bc;
// out[n] = sp/(1+sp) for every node n of this block's graphs (batch sorted ->
// contiguous node range). Block zeroes its own g_S slice for the next replay.
__global__ __launch_bounds__(H) void mlp_kernel(
        const int* __restrict__ batch, int N,
        const float* __restrict__ W1, const float* __restrict__ b1,
        const float* __restrict__ W2, const float* __restrict__ b2,
        const float* __restrict__ Wc, const float* __restrict__ bc,
        float* __restrict__ out) {
    __shared__ float sS[GPB][D];
    __shared__ float sH[GPB][H];
    __shared__ int   sbound[GPB + 1];
    __shared__ float sv[GPB];

    const int g0 = blockIdx.x * GPB;
    const int t  = threadIdx.x;   // 0..H-1

    for (int i = t; i < GPB * D; i += H)
        sS[i / D][i % D] = g_S[g0 * D + i];

    if (t <= GPB)
        sbound[t] = lower_bound_i(batch, N, g0 + t);
    __syncthreads();

    // re-zero this block's g_S slice for the next graph replay
    for (int i = t; i < GPB * D; i += H)
        g_S[g0 * D + i] = 0.f;

    // Layer 1 (column t for GPB graphs), then scale by node count (= agg2)
    float acc1[GPB];
    #pragma unroll
    for (int q = 0; q < GPB; q++) acc1[q] = b1[t];
    #pragma unroll 8
    for (int k = 0; k < D; k++) {
        float w = W1[k * H + t];
        #pragma unroll
        for (int q = 0; q < GPB; q++) acc1[q] = fmaf(sS[q][k], w, acc1[q]);
    }
    #pragma unroll
    for (int q = 0; q < GPB; q++) {
        float cnt = (float)(sbound[q + 1] - sbound[q]);
        sH[q][t] = fmaxf(acc1[q], 0.f) * cnt;
    }
    __syncthreads();

    // Layer 2
    float acc2[GPB];
    #pragma unroll
    for (int q = 0; q < GPB; q++) acc2[q] = b2[t];
    #pragma unroll 8
    for (int k = 0; k < H; k++) {
        float w = W2[k * H + t];
        #pragma unroll
        for (int q = 0; q < GPB; q++) acc2[q] = fmaf(sH[q][k], w, acc2[q]);
    }

    // Confidence head partials + warp-shuffle reduction
    float wc = Wc[t];
    float part[GPB];
    #pragma unroll
    for (int q = 0; q < GPB; q++) part[q] = fmaxf(acc2[q], 0.f) * wc;

    #pragma unroll
    for (int q = 0; q < GPB; q++) {
        float v = part[q];
        #pragma unroll
        for (int s = 16; s > 0; s >>= 1)
            v += __shfl_down_sync(0xFFFFFFFFu, v, s);
        part[q] = v;
    }
    __syncthreads();   // sH reads (layer 2) done; reuse for warp partials
    const int lane = t & 31;
    const int warp = t >> 5;   // 0..7
    if (lane == 0) {
        #pragma unroll
        for (int q = 0; q < GPB; q++) sH[q][warp] = part[q];
    }
    __syncthreads();

    if (t < GPB) {
        float c = bc[0];
        #pragma unroll
        for (int w = 0; w < H / 32; w++) c += sH[t][w];
        float sp = fmaxf(c, 0.f) + log1pf(expf(-fabsf(c)));
        sv[t] = sp / (1.f + sp);
    }
    __syncthreads();

    // Fused scatter: this block's graphs own nodes [sbound[0], sbound[GPB])
    const int lo = sbound[0], hi = sbound[GPB];
    for (int n = lo + t; n < hi; n += H)
        out[n] = sv[batch[n] - g0];
}

// ---------------------------------------------------------------------------
extern "C" void kernel_launch(void* const* d_in, const int* in_sizes, int n_in,
                              void* d_out, int out_size) {
    const float* x     = (const float*)d_in[0];
    const int*   batch = (const int*)d_in[1];
    const float* W1    = (const float*)d_in[2];
    const float* b1    = (const float*)d_in[3];
    const float* W2    = (const float*)d_in[4];
    const float* b2    = (const float*)d_in[5];
    const float* Wc    = (const float*)d_in[6];
    const float* bc    = (const float*)d_in[7];
    float*       out   = (float*)d_out;

    const int N = in_sizes[1];

    int segBlocks = (N + RPB - 1) / RPB;
    segsum_kernel<<<segBlocks, RPB>>>(
        reinterpret_cast<const float4*>(x), batch, N);

    mlp_kernel<<<NUM_GRAPHS / GPB, H>>>(batch, N, W1, b1, W2, b2, Wc, bc, out);
}

// round 5
// speedup vs baseline: 1.7476x; 1.3774x over previous
#include <cuda_runtime.h>

#define NUM_GRAPHS 512
#define D 128
#define H 256
#define GPB 4             // graphs per MLP block
#define KT 16             // K-tile for weight staging

#define SEG_T   256       // segsum threads/block (8 warps)
#define SEG_RPW 16        // rows per warp
#define SEG_RPB 128       // rows per block (8 * 16)

// Scratch (allocation-free rule): zero-initialized at load; mlp_kernel
// re-zeroes its own slice after consumption so each graph replay starts clean.
__device__ float g_S[NUM_GRAPHS * D];

// ---------------------------------------------------------------------------
__device__ __forceinline__ void facc(float4& a, float4 v) {
    a.x += v.x; a.y += v.y; a.z += v.z; a.w += v.w;
}
__device__ __forceinline__ void flush_acc(int g, int lane, float4 a) {
    float* p = &g_S[g * D + lane * 4];
    atomicAdd(p + 0, a.x);
    atomicAdd(p + 1, a.y);
    atomicAdd(p + 2, a.z);
    atomicAdd(p + 3, a.w);
}

// Segment sum over sorted batch. Warp owns SEG_RPW contiguous rows; lane owns
// one float4 column chunk. Single-graph windows take a fully unrolled
// branch-free path (16 independent LDG.128 ptxas can front-batch).
__global__ __launch_bounds__(SEG_T) void segsum_kernel(
        const float4* __restrict__ x4, const int* __restrict__ batch, int N) {
    __shared__ int sb[SEG_RPB];
    const int t = threadIdx.x;
    const int blockStart = blockIdx.x * SEG_RPB;
    const int rows = min(N - blockStart, SEG_RPB);

    if (t < rows) sb[t] = batch[blockStart + t];
    __syncthreads();

    const int lane = t & 31;
    const int warp = t >> 5;
    const int r0 = warp * SEG_RPW;
    if (r0 >= rows) return;
    const int r1 = min(r0 + SEG_RPW, rows);

    const float4* xp = x4 + (size_t)blockStart * (D / 4) + lane;

    const int gF = sb[r0];
    const int gL = sb[r1 - 1];

    if (gF == gL && r1 - r0 == SEG_RPW) {
        // Full single-graph window: branch-free, maximal load batching.
        float4 a0 = make_float4(0.f, 0.f, 0.f, 0.f);
        float4 a1 = a0, a2 = a0, a3 = a0;
        #pragma unroll
        for (int k = 0; k < SEG_RPW; k += 4) {
            float4 v0 = xp[(size_t)(r0 + k + 0) * (D / 4)];
            float4 v1 = xp[(size_t)(r0 + k + 1) * (D / 4)];
            float4 v2 = xp[(size_t)(r0 + k + 2) * (D / 4)];
            float4 v3 = xp[(size_t)(r0 + k + 3) * (D / 4)];
            facc(a0, v0); facc(a1, v1); facc(a2, v2); facc(a3, v3);
        }
        facc(a0, a1); facc(a2, a3); facc(a0, a2);
        flush_acc(gF, lane, a0);
    } else if (gF == gL) {
        float4 a = make_float4(0.f, 0.f, 0.f, 0.f);
        for (int i = r0; i < r1; i++) facc(a, xp[(size_t)i * (D / 4)]);
        flush_acc(gF, lane, a);
    } else {
        // Window spans >=2 graphs: run-length loop (warp-uniform branch).
        float4 acc = make_float4(0.f, 0.f, 0.f, 0.f);
        int cur = gF;
        for (int i = r0; i < r1; i++) {
            int g = sb[i];
            float4 v = xp[(size_t)i * (D / 4)];
            if (g != cur) {
                flush_acc(cur, lane, acc);
                cur = g;
                acc = v;
            } else {
                facc(acc, v);
            }
        }
        flush_acc(cur, lane, acc);
    }
}

// ---------------------------------------------------------------------------
// Warp-cooperative lower_bound on sorted int array: 32-ary search, ~4 rounds.
__device__ __forceinline__ int warp_lower_bound(const int* __restrict__ a,
                                                int n, int v, int lane) {
    int lo = 0, hi = n;    // invariant: answer in [lo, hi]
    while (hi - lo > 32) {
        int span = hi - lo;
        int idx = lo + (int)(((long long)span * lane) >> 5);
        int av = a[idx];
        unsigned m = __ballot_sync(0xFFFFFFFFu, av < v);
        int c = __popc(m);                       // lanes 0..c-1 have a[p]<v
        int nlo = (c > 0) ? lo + (int)(((long long)span * (c - 1)) >> 5) + 1 : lo;
        int nhi = (c < 32) ? lo + (int)(((long long)span * c) >> 5) : hi;
        lo = nlo; hi = nhi;
    }
    int idx = lo + lane;
    bool lt = (idx < hi) ? (a[idx] < v) : false;
    unsigned m = __ballot_sync(0xFFFFFFFFu, lt);
    return lo + __popc(m);
}

// Per-graph MLP + fused scatter + g_S re-zero.
// Weights staged through double-buffered smem K-tiles (coalesced float4 loads
// into a register buffer, overlapped with compute on the other buffer).
__global__ __launch_bounds__(H) void mlp_kernel(
        const int* __restrict__ batch, int N,
        const float* __restrict__ W1, const float* __restrict__ b1,
        const float* __restrict__ W2, const float* __restrict__ b2,
        const float* __restrict__ Wc, const float* __restrict__ bc,
        float* __restrict__ out) {
    __shared__ float sW[2][KT][H];   // 32 KB
    __shared__ float sS[GPB][D];     // 2 KB
    __shared__ float sH[GPB][H];     // 4 KB
    __shared__ int   sbound[GPB + 1];
    __shared__ float sv[GPB];

    const int g0 = blockIdx.x * GPB;
    const int t  = threadIdx.x;      // 0..255
    const int lane = t & 31;
    const int warp = t >> 5;

    // Stage per-graph sums; zero slice for the next replay (same thread
    // reads and zeroes the same elements -> no hazard).
    #pragma unroll
    for (int i = t; i < GPB * D; i += H) {
        sS[i / D][i % D] = g_S[g0 * D + i];
        g_S[g0 * D + i] = 0.f;
    }

    // Node boundaries: warps 0..GPB run parallel 32-ary searches.
    if (warp <= GPB) {
        int r = warp_lower_bound(batch, N, g0 + warp, lane);
        if (lane == 0) sbound[warp] = r;
    }

    // ---- Layer 1, tiled over K (D/KT = 8 tiles) ----
    float4 rw[4];
    {   // preload tile 0
        const float4* wp = reinterpret_cast<const float4*>(W1);
        #pragma unroll
        for (int j = 0; j < 4; j++) rw[j] = wp[t + j * 256];
    }
    __syncthreads();
    #pragma unroll
    for (int j = 0; j < 4; j++)
        reinterpret_cast<float4*>(&sW[0][0][0])[t + j * 256] = rw[j];

    float acc1[GPB];
    #pragma unroll
    for (int q = 0; q < GPB; q++) acc1[q] = b1[t];

    int cur = 0;
    const int T1 = D / KT;
    for (int i = 0; i < T1; i++) {
        // prefetch next tile (or W2 tile 0) into registers
        const float4* wp = (i + 1 < T1)
            ? reinterpret_cast<const float4*>(W1 + (i + 1) * KT * H)
            : reinterpret_cast<const float4*>(W2);
        #pragma unroll
        for (int j = 0; j < 4; j++) rw[j] = wp[t + j * 256];

        __syncthreads();   // sW[cur] ready for everyone
        #pragma unroll
        for (int kk = 0; kk < KT; kk++) {
            float w = sW[cur][kk][t];
            int k = i * KT + kk;
            #pragma unroll
            for (int q = 0; q < GPB; q++)
                acc1[q] = fmaf(sS[q][k], w, acc1[q]);
        }
        #pragma unroll
        for (int j = 0; j < 4; j++)
            reinterpret_cast<float4*>(&sW[cur ^ 1][0][0])[t + j * 256] = rw[j];
        cur ^= 1;
    }

    __syncthreads();       // all layer-1 compute done; sbound visible
    #pragma unroll
    for (int q = 0; q < GPB; q++) {
        float cnt = (float)(sbound[q + 1] - sbound[q]);
        sH[q][t] = fmaxf(acc1[q], 0.f) * cnt;     // relu + count-scale (= agg2)
    }

    // ---- Layer 2, tiled over K (H/KT = 16 tiles) ----
    float acc2[GPB];
    #pragma unroll
    for (int q = 0; q < GPB; q++) acc2[q] = b2[t];

    const int T2 = H / KT;
    for (int i = 0; i < T2; i++) {
        if (i + 1 < T2) {
            const float4* wp = reinterpret_cast<const float4*>(W2 + (i + 1) * KT * H);
            #pragma unroll
            for (int j = 0; j < 4; j++) rw[j] = wp[t + j * 256];
        }
        __syncthreads();   // sW[cur] ready; first iter also covers sH writes
        #pragma unroll
        for (int kk = 0; kk < KT; kk++) {
            float w = sW[cur][kk][t];
            int k = i * KT + kk;
            #pragma unroll
            for (int q = 0; q < GPB; q++)
                acc2[q] = fmaf(sH[q][k], w, acc2[q]);
        }
        if (i + 1 < T2) {
            #pragma unroll
            for (int j = 0; j < 4; j++)
                reinterpret_cast<float4*>(&sW[cur ^ 1][0][0])[t + j * 256] = rw[j];
        }
        cur ^= 1;
    }

    // ---- Confidence head + softplus ----
    float wc = Wc[t];
    float part[GPB];
    #pragma unroll
    for (int q = 0; q < GPB; q++) part[q] = fmaxf(acc2[q], 0.f) * wc;

    #pragma unroll
    for (int q = 0; q < GPB; q++) {
        float v = part[q];
        #pragma unroll
        for (int s = 16; s > 0; s >>= 1)
            v += __shfl_down_sync(0xFFFFFFFFu, v, s);
        part[q] = v;
    }
    __syncthreads();       // sH reads done; reuse row 0 region for partials
    if (lane == 0) {
        #pragma unroll
        for (int q = 0; q < GPB; q++) sH[q][warp] = part[q];
    }
    __syncthreads();

    if (t < GPB) {
        float c = bc[0];
        #pragma unroll
        for (int w = 0; w < H / 32; w++) c += sH[t][w];
        float sp = fmaxf(c, 0.f) + log1pf(expf(-fabsf(c)));
        sv[t] = sp / (1.f + sp);
    }
    __syncthreads();

    // ---- Fused scatter: block's graphs own contiguous nodes [lo, hi) ----
    const int lo = sbound[0], hi = sbound[GPB];
    for (int n = lo + t; n < hi; n += H)
        out[n] = sv[batch[n] - g0];
}

// ---------------------------------------------------------------------------
extern "C" void kernel_launch(void* const* d_in, const int* in_sizes, int n_in,
                              void* d_out, int out_size) {
    const float* x     = (const float*)d_in[0];
    const int*   batch = (const int*)d_in[1];
    const float* W1    = (const float*)d_in[2];
    const float* b1    = (const float*)d_in[3];
    const float* W2    = (const float*)d_in[4];
    const float* b2    = (const float*)d_in[5];
    const float* Wc    = (const float*)d_in[6];
    const float* bc    = (const float*)d_in[7];
    float*       out   = (float*)d_out;

    const int N = in_sizes[1];

    int segBlocks = (N + SEG_RPB - 1) / SEG_RPB;
    segsum_kernel<<<segBlocks, SEG_T>>>(
        reinterpret_cast<const float4*>(x), batch, N);

    mlp_kernel<<<NUM_GRAPHS / GPB, H>>>(batch, N, W1, b1, W2, b2, Wc, bc, out);
}

// round 6
// speedup vs baseline: 1.7559x; 1.0047x over previous
#include <cuda_runtime.h>

#define NUM_GRAPHS 512
#define D 128
#define H 256
#define GPB 4             // graphs per MLP block
#define MLP_T 512         // MLP threads per block (2-way K-split over 256 cols)
#define ST 16             // rows per weight stage

#define SEG_T   256       // segsum threads/block (8 warps)
#define SEG_RPW 16        // rows per warp
#define SEG_RPB 128       // rows per block

// Scratch (allocation-free rule): zero-initialized at load; mlp_kernel
// re-zeroes its own slice after consumption so each graph replay starts clean.
__device__ float g_S[NUM_GRAPHS * D];

// ---------------------------------------------------------------------------
__device__ __forceinline__ void facc(float4& a, float4 v) {
    a.x += v.x; a.y += v.y; a.z += v.z; a.w += v.w;
}
__device__ __forceinline__ void flush_acc(int g, int lane, float4 a) {
    float* p = &g_S[g * D + lane * 4];
    atomicAdd(p + 0, a.x);
    atomicAdd(p + 1, a.y);
    atomicAdd(p + 2, a.z);
    atomicAdd(p + 3, a.w);
}

// Segment sum over sorted batch. Warp owns SEG_RPW contiguous rows; lane owns
// one float4 column chunk. Single-graph windows: fully unrolled batched loads.
__global__ __launch_bounds__(SEG_T) void segsum_kernel(
        const float4* __restrict__ x4, const int* __restrict__ batch, int N) {
    __shared__ int sb[SEG_RPB];
    const int t = threadIdx.x;
    const int blockStart = blockIdx.x * SEG_RPB;
    const int rows = min(N - blockStart, SEG_RPB);

    if (t < rows) sb[t] = batch[blockStart + t];
    __syncthreads();

    const int lane = t & 31;
    const int warp = t >> 5;
    const int r0 = warp * SEG_RPW;
    if (r0 >= rows) return;
    const int r1 = min(r0 + SEG_RPW, rows);

    const float4* xp = x4 + (size_t)blockStart * (D / 4) + lane;

    const int gF = sb[r0];
    const int gL = sb[r1 - 1];

    if (gF == gL && r1 - r0 == SEG_RPW) {
        float4 a0 = make_float4(0.f, 0.f, 0.f, 0.f);
        float4 a1 = a0, a2 = a0, a3 = a0;
        #pragma unroll
        for (int k = 0; k < SEG_RPW; k += 4) {
            float4 v0 = xp[(size_t)(r0 + k + 0) * (D / 4)];
            float4 v1 = xp[(size_t)(r0 + k + 1) * (D / 4)];
            float4 v2 = xp[(size_t)(r0 + k + 2) * (D / 4)];
            float4 v3 = xp[(size_t)(r0 + k + 3) * (D / 4)];
            facc(a0, v0); facc(a1, v1); facc(a2, v2); facc(a3, v3);
        }
        facc(a0, a1); facc(a2, a3); facc(a0, a2);
        flush_acc(gF, lane, a0);
    } else if (gF == gL) {
        float4 a = make_float4(0.f, 0.f, 0.f, 0.f);
        for (int i = r0; i < r1; i++) facc(a, xp[(size_t)i * (D / 4)]);
        flush_acc(gF, lane, a);
    } else {
        float4 acc = make_float4(0.f, 0.f, 0.f, 0.f);
        int cur = gF;
        for (int i = r0; i < r1; i++) {
            int g = sb[i];
            float4 v = xp[(size_t)i * (D / 4)];
            if (g != cur) {
                flush_acc(cur, lane, acc);
                cur = g;
                acc = v;
            } else {
                facc(acc, v);
            }
        }
        flush_acc(cur, lane, acc);
    }
}

// ---------------------------------------------------------------------------
__device__ __forceinline__ int warp_lower_bound(const int* __restrict__ a,
                                                int n, int v, int lane) {
    int lo = 0, hi = n;
    while (hi - lo > 32) {
        int span = hi - lo;
        int idx = lo + (int)(((long long)span * lane) >> 5);
        int av = a[idx];
        unsigned m = __ballot_sync(0xFFFFFFFFu, av < v);
        int c = __popc(m);
        int nlo = (c > 0) ? lo + (int)(((long long)span * (c - 1)) >> 5) + 1 : lo;
        int nhi = (c < 32) ? lo + (int)(((long long)span * c) >> 5) : hi;
        lo = nlo; hi = nhi;
    }
    int idx = lo + lane;
    bool lt = (idx < hi) ? (a[idx] < v) : false;
    unsigned m = __ballot_sync(0xFFFFFFFFu, lt);
    return lo + __popc(m);
}

// Per-graph MLP + fused scatter + g_S re-zero. 512 threads: thread =
// (half, col); each half accumulates half of K, partials combined in smem.
// Weights flow through a double-buffered 16-row smem stage pipeline.
__global__ __launch_bounds__(MLP_T) void mlp_kernel(
        const int* __restrict__ batch, int N,
        const float* __restrict__ W1, const float* __restrict__ b1,
        const float* __restrict__ W2, const float* __restrict__ b2,
        const float* __restrict__ Wc, const float* __restrict__ bc,
        float* __restrict__ out) {
    __shared__ float sW[2][ST][H];      // 32 KB double-buffered weight stage
    __shared__ float sS[GPB][D];        // 2 KB  per-graph input sums
    __shared__ float sH[GPB][H];        // 4 KB  h1 (layer-2 activations)
    __shared__ float sP[2][GPB][H];     // 8 KB  per-half partial accumulators
    __shared__ float sRed[GPB][4];
    __shared__ int   sbound[GPB + 1];
    __shared__ float sv[GPB];

    const int g0   = blockIdx.x * GPB;
    const int t    = threadIdx.x;       // 0..511
    const int col  = t & (H - 1);       // 0..255
    const int half = t >> 8;            // 0..1
    const int lane = t & 31;
    const int warp = t >> 5;            // 0..15

    // Stage per-graph sums; zero slice for next replay (1 elem/thread).
    if (t < GPB * D) {
        sS[t / D][t % D] = g_S[g0 * D + t];
        g_S[g0 * D + t] = 0.f;
    }

    // Node boundaries: warps 0..GPB run parallel 32-ary searches.
    if (warp <= GPB) {
        int r = warp_lower_bound(batch, N, g0 + warp, lane);
        if (lane == 0) sbound[warp] = r;
    }

    // ---- Layer 1: K=128, 8 stages of 16 rows; this half does 8 k/stage ----
    float4 rw[2];
    {   // preload stage 0 (16*256 floats = 1024 float4, 2 per thread)
        const float4* wp = reinterpret_cast<const float4*>(W1);
        rw[0] = wp[t]; rw[1] = wp[t + MLP_T];
    }
    __syncthreads();
    reinterpret_cast<float4*>(&sW[0][0][0])[t]         = rw[0];
    reinterpret_cast<float4*>(&sW[0][0][0])[t + MLP_T] = rw[1];

    float acc[GPB];
    #pragma unroll
    for (int q = 0; q < GPB; q++) acc[q] = 0.f;

    int cur = 0;
    const int T1 = D / ST;   // 8
    for (int i = 0; i < T1; i++) {
        const float4* wp = (i + 1 < T1)
            ? reinterpret_cast<const float4*>(W1 + (i + 1) * ST * H)
            : reinterpret_cast<const float4*>(W2);
        rw[0] = wp[t]; rw[1] = wp[t + MLP_T];

        __syncthreads();   // sW[cur] visible
        const int kb = i * ST + half * (ST / 2);
        #pragma unroll
        for (int j = 0; j < 2; j++) {
            float4 s4[GPB];
            #pragma unroll
            for (int q = 0; q < GPB; q++)
                s4[q] = *reinterpret_cast<const float4*>(&sS[q][kb + j * 4]);
            #pragma unroll
            for (int kk = 0; kk < 4; kk++) {
                float w = sW[cur][half * (ST / 2) + j * 4 + kk][col];
                acc[0] = fmaf((&s4[0].x)[kk], w, acc[0]);
                acc[1] = fmaf((&s4[1].x)[kk], w, acc[1]);
                acc[2] = fmaf((&s4[2].x)[kk], w, acc[2]);
                acc[3] = fmaf((&s4[3].x)[kk], w, acc[3]);
            }
        }
        reinterpret_cast<float4*>(&sW[cur ^ 1][0][0])[t]         = rw[0];
        reinterpret_cast<float4*>(&sW[cur ^ 1][0][0])[t + MLP_T] = rw[1];
        cur ^= 1;
    }

    // combine halves -> h1 = relu(b1 + p0 + p1) * cnt   (cnt scale = agg2)
    #pragma unroll
    for (int q = 0; q < GPB; q++) sP[half][q][col] = acc[q];
    __syncthreads();
    #pragma unroll
    for (int i = t; i < GPB * H; i += MLP_T) {
        int q = i >> 8, c = i & (H - 1);
        float cnt = (float)(sbound[q + 1] - sbound[q]);
        float h = b1[c] + sP[0][q][c] + sP[1][q][c];
        sH[q][c] = fmaxf(h, 0.f) * cnt;
    }

    // ---- Layer 2: K=256, 16 stages of 16 rows ----
    #pragma unroll
    for (int q = 0; q < GPB; q++) acc[q] = 0.f;

    const int T2 = H / ST;   // 16
    for (int i = 0; i < T2; i++) {
        if (i + 1 < T2) {
            const float4* wp = reinterpret_cast<const float4*>(W2 + (i + 1) * ST * H);
            rw[0] = wp[t]; rw[1] = wp[t + MLP_T];
        }
        __syncthreads();   // sW[cur] visible (iter 0: also guards sH writes)
        const int kb = i * ST + half * (ST / 2);
        #pragma unroll
        for (int j = 0; j < 2; j++) {
            float4 s4[GPB];
            #pragma unroll
            for (int q = 0; q < GPB; q++)
                s4[q] = *reinterpret_cast<const float4*>(&sH[q][kb + j * 4]);
            #pragma unroll
            for (int kk = 0; kk < 4; kk++) {
                float w = sW[cur][half * (ST / 2) + j * 4 + kk][col];
                acc[0] = fmaf((&s4[0].x)[kk], w, acc[0]);
                acc[1] = fmaf((&s4[1].x)[kk], w, acc[1]);
                acc[2] = fmaf((&s4[2].x)[kk], w, acc[2]);
                acc[3] = fmaf((&s4[3].x)[kk], w, acc[3]);
            }
        }
        if (i + 1 < T2) {
            reinterpret_cast<float4*>(&sW[cur ^ 1][0][0])[t]         = rw[0];
            reinterpret_cast<float4*>(&sW[cur ^ 1][0][0])[t + MLP_T] = rw[1];
        }
        cur ^= 1;
    }

    // ---- Head: combine halves, c = sum_col relu(h2)*Wc, softplus ----
    #pragma unroll
    for (int q = 0; q < GPB; q++) sP[half][q][col] = acc[q];
    __syncthreads();

    {
        int q  = t >> 7;            // 0..3 (128 threads per graph)
        int c0 = t & 127;
        float v = 0.f;
        #pragma unroll
        for (int rep = 0; rep < 2; rep++) {
            int c = c0 + rep * 128;
            float h = b2[c] + sP[0][q][c] + sP[1][q][c];
            v += fmaxf(h, 0.f) * Wc[c];
        }
        #pragma unroll
        for (int s = 16; s > 0; s >>= 1)
            v += __shfl_down_sync(0xFFFFFFFFu, v, s);
        if (lane == 0) sRed[q][warp & 3] = v;
    }
    __syncthreads();

    if (t < GPB) {
        float c = bc[0] + sRed[t][0] + sRed[t][1] + sRed[t][2] + sRed[t][3];
        float sp = fmaxf(c, 0.f) + log1pf(expf(-fabsf(c)));
        sv[t] = sp / (1.f + sp);
    }
    __syncthreads();

    // ---- Fused scatter over this block's contiguous node range ----
    const int lo = sbound[0], hi = sbound[GPB];
    for (int n = lo + t; n < hi; n += MLP_T)
        out[n] = sv[batch[n] - g0];
}

// ---------------------------------------------------------------------------
extern "C" void kernel_launch(void* const* d_in, const int* in_sizes, int n_in,
                              void* d_out, int out_size) {
    const float* x     = (const float*)d_in[0];
    const int*   batch = (const int*)d_in[1];
    const float* W1    = (const float*)d_in[2];
    const float* b1    = (const float*)d_in[3];
    const float* W2    = (const float*)d_in[4];
    const float* b2    = (const float*)d_in[5];
    const float* Wc    = (const float*)d_in[6];
    const float* bc    = (const float*)d_in[7];
    float*       out   = (float*)d_out;

    const int N = in_sizes[1];

    int segBlocks = (N + SEG_RPB - 1) / SEG_RPB;
    segsum_kernel<<<segBlocks, SEG_T>>>(
        reinterpret_cast<const float4*>(x), batch, N);

    mlp_kernel<<<NUM_GRAPHS / GPB, MLP_T>>>(batch, N, W1, b1, W2, b2, Wc, bc, out);
}

// round 7
// speedup vs baseline: 2.0583x; 1.1722x over previous
#include <cuda_runtime.h>

#define NUM_GRAPHS 512
#define D 128
#define H 256
#define GPB 4             // graphs per MLP block
#define MLP_T 1024        // 256 cols x 4 K-quarters

#define SEG_T   256       // segsum threads/block (8 warps)
#define SEG_RPW 32        // rows per warp (two 16-row subtiles)
#define SEG_RPB 256       // rows per block

// Scratch (allocation-free rule): zero-initialized at load; mlp_kernel
// re-zeroes its slice after consumption so each graph replay starts clean.
__device__ float g_S[NUM_GRAPHS * D];

// ---------------------------------------------------------------------------
__device__ __forceinline__ void facc(float4& a, float4 v) {
    a.x += v.x; a.y += v.y; a.z += v.z; a.w += v.w;
}
__device__ __forceinline__ void flush_acc(int g, int lane, float4 a) {
    float* p = &g_S[g * D + lane * 4];
    atomicAdd(p + 0, a.x);
    atomicAdd(p + 1, a.y);
    atomicAdd(p + 2, a.z);
    atomicAdd(p + 3, a.w);
}

// Segment sum over sorted batch. Warp owns 32 contiguous rows as two 16-row
// subtiles; lane owns one float4 column chunk. Single-graph subtiles take a
// fully unrolled path with 16 independent LDG.128 in flight.
__global__ __launch_bounds__(SEG_T) void segsum_kernel(
        const float4* __restrict__ x4, const int* __restrict__ batch, int N) {
    __shared__ int sb[SEG_RPB];
    const int t = threadIdx.x;
    const int blockStart = blockIdx.x * SEG_RPB;
    const int rows = min(N - blockStart, SEG_RPB);

    if (t < rows) sb[t] = batch[blockStart + t];
    __syncthreads();

    const int lane = t & 31;
    const int warp = t >> 5;
    const float4* xp = x4 + (size_t)blockStart * (D / 4) + lane;

    #pragma unroll
    for (int sub = 0; sub < 2; sub++) {
        const int r0 = warp * SEG_RPW + sub * 16;
        if (r0 >= rows) break;
        const int r1 = min(r0 + 16, rows);

        const int gF = sb[r0];
        const int gL = sb[r1 - 1];

        if (gF == gL && r1 - r0 == 16) {
            float4 a0 = make_float4(0.f, 0.f, 0.f, 0.f);
            float4 a1 = a0, a2 = a0, a3 = a0;
            #pragma unroll
            for (int k = 0; k < 16; k += 4) {
                float4 v0 = xp[(size_t)(r0 + k + 0) * (D / 4)];
                float4 v1 = xp[(size_t)(r0 + k + 1) * (D / 4)];
                float4 v2 = xp[(size_t)(r0 + k + 2) * (D / 4)];
                float4 v3 = xp[(size_t)(r0 + k + 3) * (D / 4)];
                facc(a0, v0); facc(a1, v1); facc(a2, v2); facc(a3, v3);
            }
            facc(a0, a1); facc(a2, a3); facc(a0, a2);
            flush_acc(gF, lane, a0);
        } else if (gF == gL) {
            float4 a = make_float4(0.f, 0.f, 0.f, 0.f);
            for (int i = r0; i < r1; i++) facc(a, xp[(size_t)i * (D / 4)]);
            flush_acc(gF, lane, a);
        } else {
            float4 acc = make_float4(0.f, 0.f, 0.f, 0.f);
            int cur = gF;
            for (int i = r0; i < r1; i++) {
                int g = sb[i];
                float4 v = xp[(size_t)i * (D / 4)];
                if (g != cur) {
                    flush_acc(cur, lane, acc);
                    cur = g;
                    acc = v;
                } else {
                    facc(acc, v);
                }
            }
            flush_acc(cur, lane, acc);
        }
    }
}

// ---------------------------------------------------------------------------
__device__ __forceinline__ int warp_lower_bound(const int* __restrict__ a,
                                                int n, int v, int lane) {
    int lo = 0, hi = n;
    while (hi - lo > 32) {
        int span = hi - lo;
        int idx = lo + (int)(((long long)span * lane) >> 5);
        int av = a[idx];
        unsigned m = __ballot_sync(0xFFFFFFFFu, av < v);
        int c = __popc(m);
        int nlo = (c > 0) ? lo + (int)(((long long)span * (c - 1)) >> 5) + 1 : lo;
        int nhi = (c < 32) ? lo + (int)(((long long)span * c) >> 5) : hi;
        lo = nlo; hi = nhi;
    }
    int idx = lo + lane;
    bool lt = (idx < hi) ? (a[idx] < v) : false;
    unsigned m = __ballot_sync(0xFFFFFFFFu, lt);
    return lo + __popc(m);
}

// Per-graph MLP + fused scatter + g_S re-zero.
// 1024 threads: col = t&255, K-quarter qr = t>>8. Weights load straight from
// gmem to registers (coalesced, 16-deep independent batches) — no smem
// staging, no per-stage syncs. One partial-combine per layer.
__global__ __launch_bounds__(MLP_T) void mlp_kernel(
        const int* __restrict__ batch, int N,
        const float* __restrict__ W1, const float* __restrict__ b1,
        const float* __restrict__ W2, const float* __restrict__ b2,
        const float* __restrict__ Wc, const float* __restrict__ bc,
        float* __restrict__ out) {
    __shared__ float sS[GPB][D];        // 2 KB
    __shared__ float sH[GPB][H];        // 4 KB
    __shared__ float sP[4][GPB][H];     // 16 KB per-quarter partials
    __shared__ float sRed[GPB][8];
    __shared__ int   sbound[GPB + 1];
    __shared__ float sv[GPB];

    const int g0   = blockIdx.x * GPB;
    const int t    = threadIdx.x;       // 0..1023
    const int col  = t & (H - 1);       // 0..255
    const int qr   = t >> 8;            // 0..3
    const int lane = t & 31;
    const int warp = t >> 5;            // 0..31

    // Stage per-graph sums; zero slice for next replay (t<512 covers it).
    if (t < GPB * D) {
        sS[t / D][t % D] = g_S[g0 * D + t];
        g_S[g0 * D + t] = 0.f;
    }
    // Node boundaries: warps 0..GPB run parallel 32-ary searches.
    if (warp <= GPB) {
        int r = warp_lower_bound(batch, N, g0 + warp, lane);
        if (lane == 0) sbound[warp] = r;
    }
    __syncthreads();

    // ---- Layer 1: qr owns k in [qr*32, qr*32+32), chunks of 16 ----
    float acc[GPB];
    #pragma unroll
    for (int q = 0; q < GPB; q++) acc[q] = 0.f;

    #pragma unroll
    for (int c = 0; c < 2; c++) {
        const int kb = qr * 32 + c * 16;
        float w[16];
        #pragma unroll
        for (int j = 0; j < 16; j++) w[j] = W1[(kb + j) * H + col];
        #pragma unroll
        for (int j = 0; j < 16; j += 4) {
            float4 s0 = *reinterpret_cast<const float4*>(&sS[0][kb + j]);
            float4 s1 = *reinterpret_cast<const float4*>(&sS[1][kb + j]);
            float4 s2 = *reinterpret_cast<const float4*>(&sS[2][kb + j]);
            float4 s3 = *reinterpret_cast<const float4*>(&sS[3][kb + j]);
            #pragma unroll
            for (int kk = 0; kk < 4; kk++) {
                float ww = w[j + kk];
                acc[0] = fmaf((&s0.x)[kk], ww, acc[0]);
                acc[1] = fmaf((&s1.x)[kk], ww, acc[1]);
                acc[2] = fmaf((&s2.x)[kk], ww, acc[2]);
                acc[3] = fmaf((&s3.x)[kk], ww, acc[3]);
            }
        }
    }
    #pragma unroll
    for (int q = 0; q < GPB; q++) sP[qr][q][col] = acc[q];
    __syncthreads();

    // combine quarters -> h1 = relu(b1 + Σp) * cnt  (cnt scale = agg2)
    {
        int q = t >> 8, c = t & (H - 1);   // 1024 threads == GPB*H slots
        float cnt = (float)(sbound[q + 1] - sbound[q]);
        float h = b1[c] + sP[0][q][c] + sP[1][q][c] + sP[2][q][c] + sP[3][q][c];
        sH[q][c] = fmaxf(h, 0.f) * cnt;
    }
    __syncthreads();

    // ---- Layer 2: qr owns k in [qr*64, qr*64+64), chunks of 16 ----
    #pragma unroll
    for (int q = 0; q < GPB; q++) acc[q] = 0.f;

    #pragma unroll
    for (int c = 0; c < 4; c++) {
        const int kb = qr * 64 + c * 16;
        float w[16];
        #pragma unroll
        for (int j = 0; j < 16; j++) w[j] = W2[(kb + j) * H + col];
        #pragma unroll
        for (int j = 0; j < 16; j += 4) {
            float4 s0 = *reinterpret_cast<const float4*>(&sH[0][kb + j]);
            float4 s1 = *reinterpret_cast<const float4*>(&sH[1][kb + j]);
            float4 s2 = *reinterpret_cast<const float4*>(&sH[2][kb + j]);
            float4 s3 = *reinterpret_cast<const float4*>(&sH[3][kb + j]);
            #pragma unroll
            for (int kk = 0; kk < 4; kk++) {
                float ww = w[j + kk];
                acc[0] = fmaf((&s0.x)[kk], ww, acc[0]);
                acc[1] = fmaf((&s1.x)[kk], ww, acc[1]);
                acc[2] = fmaf((&s2.x)[kk], ww, acc[2]);
                acc[3] = fmaf((&s3.x)[kk], ww, acc[3]);
            }
        }
    }
    #pragma unroll
    for (int q = 0; q < GPB; q++) sP[qr][q][col] = acc[q];
    __syncthreads();

    // ---- Head: h2 = relu(b2 + Σp); c = Σ_col h2*Wc; softplus-sigmoid ----
    {
        int q = t >> 8, c = t & (H - 1);
        float h = b2[c] + sP[0][q][c] + sP[1][q][c] + sP[2][q][c] + sP[3][q][c];
        float v = fmaxf(h, 0.f) * Wc[c];
        #pragma unroll
        for (int s = 16; s > 0; s >>= 1)
            v += __shfl_down_sync(0xFFFFFFFFu, v, s);
        if (lane == 0) sRed[q][warp & 7] = v;
    }
    __syncthreads();

    if (t < GPB) {
        float c = bc[0];
        #pragma unroll
        for (int w = 0; w < 8; w++) c += sRed[t][w];
        float sp = fmaxf(c, 0.f) + log1pf(expf(-fabsf(c)));
        sv[t] = sp / (1.f + sp);
    }
    __syncthreads();

    // ---- Fused scatter over this block's contiguous node range ----
    const int lo = sbound[0], hi = sbound[GPB];
    for (int n = lo + t; n < hi; n += MLP_T)
        out[n] = sv[batch[n] - g0];
}

// ---------------------------------------------------------------------------
extern "C" void kernel_launch(void* const* d_in, const int* in_sizes, int n_in,
                              void* d_out, int out_size) {
    const float* x     = (const float*)d_in[0];
    const int*   batch = (const int*)d_in[1];
    const float* W1    = (const float*)d_in[2];
    const float* b1    = (const float*)d_in[3];
    const float* W2    = (const float*)d_in[4];
    const float* b2    = (const float*)d_in[5];
    const float* Wc    = (const float*)d_in[6];
    const float* bc    = (const float*)d_in[7];
    float*       out   = (float*)d_out;

    const int N = in_sizes[1];

    int segBlocks = (N + SEG_RPB - 1) / SEG_RPB;
    segsum_kernel<<<segBlocks, SEG_T>>>(
        reinterpret_cast<const float4*>(x), batch, N);

    mlp_kernel<<<NUM_GRAPHS / GPB, MLP_T>>>(batch, N, W1, b1, W2, b2, Wc, bc, out);
}